// round 1
// baseline (speedup 1.0000x reference)
#include <cuda_runtime.h>
#include <cstdint>

// LateralInhibition: per-batch top-k masking, exact radix select.
// Input: membrane fp32 [8, 32, 32, 64, 64]  -> flat [8, 4194304]
// Output: membrane * mask(top-k per batch), k = int(0.1 * N) = 419430

#define BATCH 8
#define NPB   4194304            // 32*32*64*64
#define KSEL  419430u            // int(0.1 * NPB)
#define H_SIZE 4096              // 12-bit histogram
#define CAND_CAP  (1u<<20)       // per-batch candidate capacity (expected ~90K)
#define CAND2_CAP (1u<<16)       // per-batch fine-candidate capacity (expected ~30)

// -------- scratch (device globals; re-zeroed every launch) --------
__device__ unsigned g_hist1[BATCH][H_SIZE];
__device__ unsigned g_hist2[BATCH][H_SIZE];
__device__ unsigned g_candCount[BATCH];
__device__ unsigned g_cand2Count[BATCH];
__device__ int      g_b1[BATCH];
__device__ unsigned g_g1[BATCH];     // count strictly above bin b1
__device__ int      g_b2[BATCH];
__device__ unsigned g_rem[BATCH];    // remaining to pick inside exact 24-bit prefix
__device__ uint2    g_cand [BATCH][CAND_CAP];    // (key, idx)
__device__ uint2    g_cand2[BATCH][CAND2_CAP];

// order-preserving key: descending float  <=>  descending key
__device__ __forceinline__ unsigned key_of(float x) {
    unsigned u = __float_as_uint(x);
    return (u & 0x80000000u) ? ~u : (u | 0x80000000u);
}
__device__ __forceinline__ float val_of(unsigned key) {
    unsigned u = (key & 0x80000000u) ? (key & 0x7FFFFFFFu) : ~key;
    return __uint_as_float(u);
}

// -------- K0: zero scratch --------
__global__ void k_zero() {
    int tid = blockIdx.x * blockDim.x + threadIdx.x;
    int stride = gridDim.x * blockDim.x;
    unsigned* h1 = &g_hist1[0][0];
    unsigned* h2 = &g_hist2[0][0];
    for (int i = tid; i < BATCH * H_SIZE; i += stride) { h1[i] = 0u; h2[i] = 0u; }
    if (tid < BATCH) { g_candCount[tid] = 0u; g_cand2Count[tid] = 0u; }
}

// -------- K1: coarse histogram (top 12 key bits), per batch --------
__global__ void k_hist1(const float* __restrict__ in) {
    __shared__ unsigned sh[H_SIZE];
    for (int i = threadIdx.x; i < H_SIZE; i += blockDim.x) sh[i] = 0u;
    __syncthreads();

    int b = blockIdx.y;
    const float4* p = (const float4*)(in + (size_t)b * NPB);
    int n4 = NPB / 4;
    int stride = gridDim.x * blockDim.x;
    for (int i = blockIdx.x * blockDim.x + threadIdx.x; i < n4; i += stride) {
        float4 v = p[i];
        atomicAdd(&sh[key_of(v.x) >> 20], 1u);
        atomicAdd(&sh[key_of(v.y) >> 20], 1u);
        atomicAdd(&sh[key_of(v.z) >> 20], 1u);
        atomicAdd(&sh[key_of(v.w) >> 20], 1u);
    }
    __syncthreads();
    for (int i = threadIdx.x; i < H_SIZE; i += blockDim.x) {
        unsigned c = sh[i];
        if (c) atomicAdd(&g_hist1[b][i], c);
    }
}

// -------- shared suffix-scan helper: find bin where cum-from-top crosses target --------
// hist entries indexed by bin value; scan in DESCENDING key order.
__device__ void scan_find(const unsigned* __restrict__ hist, unsigned target,
                          int* out_bin, unsigned* out_above) {
    __shared__ unsigned buf0[H_SIZE];
    __shared__ unsigned buf1[H_SIZE];
    // load in descending-key order
    for (int i = threadIdx.x; i < H_SIZE; i += blockDim.x) buf0[i] = hist[H_SIZE - 1 - i];
    __syncthreads();
    unsigned* a = buf0; unsigned* t = buf1;
    for (int off = 1; off < H_SIZE; off <<= 1) {
        for (int i = threadIdx.x; i < H_SIZE; i += blockDim.x) {
            unsigned v = a[i];
            if (i >= off) v += a[i - off];
            t[i] = v;
        }
        __syncthreads();
        unsigned* tmp = a; a = t; t = tmp;
    }
    // a[] = inclusive cumulative count (from highest key down)
    for (int i = threadIdx.x; i < H_SIZE; i += blockDim.x) {
        unsigned incl = a[i];
        unsigned excl = (i > 0) ? a[i - 1] : 0u;
        if (excl < target && target <= incl) {
            *out_bin = H_SIZE - 1 - i;
            *out_above = excl;
        }
    }
    __syncthreads();
}

// -------- K2: find coarse bin b1 --------
__global__ void k_scan1() {
    int b = blockIdx.x;
    __shared__ int s_bin; __shared__ unsigned s_above;
    scan_find(g_hist1[b], KSEL, &s_bin, &s_above);
    if (threadIdx.x == 0) { g_b1[b] = s_bin; g_g1[b] = s_above; }
}

// -------- K3: partition + write provisional output + collect bin-b1 candidates
//            + histogram their next 12 key bits --------
__global__ void k_partition(const float* __restrict__ in, float* __restrict__ out) {
    __shared__ unsigned sh[H_SIZE];
    for (int i = threadIdx.x; i < H_SIZE; i += blockDim.x) sh[i] = 0u;
    __syncthreads();

    int b = blockIdx.y;
    int b1 = g_b1[b];
    const float4* p = (const float4*)(in + (size_t)b * NPB);
    float4* q = (float4*)(out + (size_t)b * NPB);
    int n4 = NPB / 4;
    int stride = gridDim.x * blockDim.x;
    int lane = threadIdx.x & 31;

    for (int i = blockIdx.x * blockDim.x + threadIdx.x; i < n4; i += stride) {
        float4 v = p[i];
        unsigned kk[4] = { key_of(v.x), key_of(v.y), key_of(v.z), key_of(v.w) };
        float vv[4] = { v.x, v.y, v.z, v.w };
        float4 o;
        o.x = ((int)(kk[0] >> 20) > b1) ? v.x : 0.0f;
        o.y = ((int)(kk[1] >> 20) > b1) ? v.y : 0.0f;
        o.z = ((int)(kk[2] >> 20) > b1) ? v.z : 0.0f;
        o.w = ((int)(kk[3] >> 20) > b1) ? v.w : 0.0f;
        q[i] = o;
        (void)vv;
        #pragma unroll
        for (int c = 0; c < 4; c++) {
            bool want = ((int)(kk[c] >> 20) == b1);
            // warp trip counts are uniform (n4 % (grid*block) == 0), ballot is safe
            unsigned m = __ballot_sync(0xFFFFFFFFu, want);
            if (want) {
                atomicAdd(&sh[(kk[c] >> 8) & 0xFFFu], 1u);
                int leader = __ffs(m) - 1;
                unsigned base = 0;
                if (lane == leader) base = atomicAdd(&g_candCount[b], (unsigned)__popc(m));
                base = __shfl_sync(m, base, leader);
                unsigned pos = base + (unsigned)__popc(m & ((1u << lane) - 1u));
                if (pos < CAND_CAP) {
                    g_cand[b][pos] = make_uint2(kk[c], (unsigned)(i * 4 + c));
                }
            }
        }
    }
    __syncthreads();
    for (int i = threadIdx.x; i < H_SIZE; i += blockDim.x) {
        unsigned c = sh[i];
        if (c) atomicAdd(&g_hist2[b][i], c);
    }
}

// -------- K4: find fine sub-bin b2 and remainder r --------
__global__ void k_scan2() {
    int b = blockIdx.x;
    unsigned target = KSEL - g_g1[b];   // >= 1 by construction
    __shared__ int s_bin; __shared__ unsigned s_above;
    scan_find(g_hist2[b], target, &s_bin, &s_above);
    if (threadIdx.x == 0) { g_b2[b] = s_bin; g_rem[b] = target - s_above; }
}

// -------- K5: resolve candidates vs 24-bit prefix --------
__global__ void k_cands(float* __restrict__ out) {
    int b = blockIdx.y;
    unsigned count = g_candCount[b];
    if (count > CAND_CAP) count = CAND_CAP;
    unsigned prefix24 = (((unsigned)g_b1[b]) << 12) | (unsigned)g_b2[b];
    float* ob = out + (size_t)b * NPB;
    unsigned stride = gridDim.x * blockDim.x;
    for (unsigned i = blockIdx.x * blockDim.x + threadIdx.x; i < count; i += stride) {
        uint2 e = g_cand[b][i];
        unsigned p24 = e.x >> 8;
        if (p24 > prefix24) {
            ob[e.y] = val_of(e.x);
        } else if (p24 == prefix24) {
            unsigned pos = atomicAdd(&g_cand2Count[b], 1u);
            if (pos < CAND2_CAP) g_cand2[b][pos] = e;
        }
    }
}

// -------- K6: exact k-th key via byte histogram; index-stable tie handling --------
__global__ void k_final(float* __restrict__ out) {
    int b = blockIdx.x;
    unsigned c = g_cand2Count[b];
    if (c > CAND2_CAP) c = CAND2_CAP;
    unsigned r = g_rem[b];
    __shared__ unsigned hist[256];
    __shared__ int s_byte; __shared__ unsigned s_t;
    for (int i = threadIdx.x; i < 256; i += blockDim.x) hist[i] = 0u;
    __syncthreads();
    for (unsigned i = threadIdx.x; i < c; i += blockDim.x)
        atomicAdd(&hist[g_cand2[b][i].x & 0xFFu], 1u);
    __syncthreads();
    if (threadIdx.x == 0) {
        unsigned acc = 0; int byte = 0; unsigned t = 0;
        for (int bb = 255; bb >= 0; bb--) {
            unsigned cnt = hist[bb];
            if (acc < r && r <= acc + cnt) { byte = bb; t = r - acc; break; }
            acc += cnt;
        }
        s_byte = byte; s_t = t;
    }
    __syncthreads();
    int byte = s_byte; unsigned t = s_t;
    float* ob = out + (size_t)b * NPB;
    // strictly above exact threshold key: include
    for (unsigned i = threadIdx.x; i < c; i += blockDim.x) {
        uint2 e = g_cand2[b][i];
        if ((int)(e.x & 0xFFu) > byte) ob[e.y] = val_of(e.x);
    }
    // ties at exact key value: keep the t with smallest flat index (top_k stability)
    for (unsigned i = threadIdx.x; i < c; i += blockDim.x) {
        uint2 e = g_cand2[b][i];
        if ((int)(e.x & 0xFFu) == byte) {
            unsigned rank = 0;
            for (unsigned j = 0; j < c; j++) {
                uint2 f = g_cand2[b][j];
                if ((int)(f.x & 0xFFu) == byte && f.y < e.y) rank++;
            }
            if (rank < t) ob[e.y] = val_of(e.x);
        }
    }
}

extern "C" void kernel_launch(void* const* d_in, const int* in_sizes, int n_in,
                              void* d_out, int out_size) {
    const float* in = (const float*)d_in[0];
    float* out = (float*)d_out;
    (void)in_sizes; (void)n_in; (void)out_size;

    dim3 big(128, BATCH, 1);   // 1024 blocks

    k_zero<<<64, 256>>>();
    k_hist1<<<big, 256>>>(in);
    k_scan1<<<BATCH, 256>>>();
    k_partition<<<big, 256>>>(in, out);
    k_scan2<<<BATCH, 256>>>();
    k_cands<<<dim3(32, BATCH, 1), 256>>>(out);
    k_final<<<BATCH, 256>>>(out);
}

// round 2
// speedup vs baseline: 2.9592x; 2.9592x over previous
#include <cuda_runtime.h>
#include <cstdint>

// LateralInhibition: per-batch top-k masking, exact radix select.
// Input: membrane fp32 [8, 32, 32, 64, 64] -> flat [8, 4194304]
// k = int(0.1 * N) = 419430 per batch.

#define BATCH 8
#define NPB   4194304
#define N4    1048576            // NPB/4
#define KSEL  419430u
#define H_SIZE 4096
#define GRIDX 128
#define TPB   256
#define TPB_TOTAL (GRIDX*TPB)    // 32768 threads per batch
#define ITERS (N4 / TPB_TOTAL)   // 32
#define SBUF_CAP 2048            // per-block candidate buffer (expected ~655)
#define CAND_CAP  (1u<<20)
#define CAND2_CAP (1u<<16)

// -------- scratch --------
__device__ unsigned g_hist1[BATCH][H_SIZE];
__device__ unsigned g_candCount[BATCH];
__device__ unsigned g_cand2Count[BATCH];
__device__ int      g_b1[BATCH];
__device__ unsigned g_g1[BATCH];     // count strictly above bin b1
__device__ int      g_b2[BATCH];
__device__ unsigned g_rem[BATCH];
__device__ uint2    g_cand [BATCH][CAND_CAP];
__device__ uint2    g_cand2[BATCH][CAND2_CAP];

// order-preserving key: descending float <=> descending unsigned key
__device__ __forceinline__ unsigned key_of(float x) {
    unsigned u = __float_as_uint(x);
    return (u & 0x80000000u) ? ~u : (u | 0x80000000u);
}
__device__ __forceinline__ float val_of(unsigned key) {
    unsigned u = (key & 0x80000000u) ? (key & 0x7FFFFFFFu) : ~key;
    return __uint_as_float(u);
}

// -------- K0: zero scratch --------
__global__ void k_zero() {
    int tid = blockIdx.x * blockDim.x + threadIdx.x;
    int stride = gridDim.x * blockDim.x;
    unsigned* h1 = &g_hist1[0][0];
    for (int i = tid; i < BATCH * H_SIZE; i += stride) h1[i] = 0u;
    if (tid < BATCH) { g_candCount[tid] = 0u; g_cand2Count[tid] = 0u; }
}

// -------- K1: coarse histogram (top 12 key bits) --------
__global__ void k_hist1(const float* __restrict__ in) {
    __shared__ unsigned sh[H_SIZE];
    for (int i = threadIdx.x; i < H_SIZE; i += blockDim.x) sh[i] = 0u;
    __syncthreads();

    int b = blockIdx.y;
    const float4* __restrict__ p = (const float4*)(in + (size_t)b * NPB);
    int base_i = blockIdx.x * blockDim.x + threadIdx.x;
    #pragma unroll 4
    for (int j = 0; j < ITERS; j++) {
        float4 v = p[base_i + j * TPB_TOTAL];
        atomicAdd(&sh[key_of(v.x) >> 20], 1u);
        atomicAdd(&sh[key_of(v.y) >> 20], 1u);
        atomicAdd(&sh[key_of(v.z) >> 20], 1u);
        atomicAdd(&sh[key_of(v.w) >> 20], 1u);
    }
    __syncthreads();
    for (int i = threadIdx.x; i < H_SIZE; i += blockDim.x) {
        unsigned c = sh[i];
        if (c) atomicAdd(&g_hist1[b][i], c);
    }
}

// -------- suffix-scan select: find bin where desc-cumulative crosses target --------
// a: histogram in normal bin order (will be clobbered). t: tmp.
__device__ __forceinline__ void scan_find2(unsigned* a, unsigned* t, unsigned target,
                                           int* s_bin, unsigned* s_above) {
    // reverse into t: t[i] = count of bin (H_SIZE-1-i)
    for (int i = threadIdx.x; i < H_SIZE; i += blockDim.x) t[i] = a[H_SIZE - 1 - i];
    __syncthreads();
    unsigned* src = t; unsigned* dst = a;
    for (int off = 1; off < H_SIZE; off <<= 1) {
        for (int i = threadIdx.x; i < H_SIZE; i += blockDim.x) {
            unsigned v = src[i];
            if (i >= off) v += src[i - off];
            dst[i] = v;
        }
        __syncthreads();
        unsigned* tmp = src; src = dst; dst = tmp;
    }
    for (int i = threadIdx.x; i < H_SIZE; i += blockDim.x) {
        unsigned incl = src[i];
        unsigned excl = (i > 0) ? src[i - 1] : 0u;
        if (excl < target && target <= incl) {
            *s_bin = H_SIZE - 1 - i;
            *s_above = excl;
        }
    }
    __syncthreads();
}

// -------- K2: coarse bin b1 --------
__global__ void k_scan1() {
    __shared__ unsigned a[H_SIZE];
    __shared__ unsigned t[H_SIZE];
    __shared__ int s_bin; __shared__ unsigned s_above;
    int b = blockIdx.x;
    for (int i = threadIdx.x; i < H_SIZE; i += blockDim.x) a[i] = g_hist1[b][i];
    __syncthreads();
    scan_find2(a, t, KSEL, &s_bin, &s_above);
    if (threadIdx.x == 0) { g_b1[b] = s_bin; g_g1[b] = s_above; }
}

// -------- K3: streaming partition + shared-buffered candidate collection --------
__global__ void k_partition(const float* __restrict__ in, float* __restrict__ out) {
    __shared__ unsigned s_cnt;
    __shared__ unsigned s_base;
    __shared__ uint2 s_buf[SBUF_CAP];
    if (threadIdx.x == 0) s_cnt = 0u;
    __syncthreads();

    int b = blockIdx.y;
    unsigned b1 = (unsigned)g_b1[b];
    const float4* __restrict__ p = (const float4*)(in + (size_t)b * NPB);
    float4* __restrict__ q = (float4*)(out + (size_t)b * NPB);
    int base_i = blockIdx.x * blockDim.x + threadIdx.x;

    #pragma unroll 4
    for (int j = 0; j < ITERS; j++) {
        int i = base_i + j * TPB_TOTAL;
        float4 v = p[i];
        unsigned k0 = key_of(v.x), k1 = key_of(v.y), k2 = key_of(v.z), k3 = key_of(v.w);
        float4 o;
        o.x = ((k0 >> 20) > b1) ? v.x : 0.0f;
        o.y = ((k1 >> 20) > b1) ? v.y : 0.0f;
        o.z = ((k2 >> 20) > b1) ? v.z : 0.0f;
        o.w = ((k3 >> 20) > b1) ? v.w : 0.0f;
        q[i] = o;
        bool c0 = ((k0 >> 20) == b1), c1 = ((k1 >> 20) == b1);
        bool c2 = ((k2 >> 20) == b1), c3 = ((k3 >> 20) == b1);
        if (c0 | c1 | c2 | c3) {
            unsigned ib = (unsigned)i * 4u;
            if (c0) { unsigned pos = atomicAdd(&s_cnt, 1u); if (pos < SBUF_CAP) s_buf[pos] = make_uint2(k0, ib + 0u); }
            if (c1) { unsigned pos = atomicAdd(&s_cnt, 1u); if (pos < SBUF_CAP) s_buf[pos] = make_uint2(k1, ib + 1u); }
            if (c2) { unsigned pos = atomicAdd(&s_cnt, 1u); if (pos < SBUF_CAP) s_buf[pos] = make_uint2(k2, ib + 2u); }
            if (c3) { unsigned pos = atomicAdd(&s_cnt, 1u); if (pos < SBUF_CAP) s_buf[pos] = make_uint2(k3, ib + 3u); }
        }
    }
    __syncthreads();
    unsigned cnt = s_cnt < SBUF_CAP ? s_cnt : SBUF_CAP;
    if (threadIdx.x == 0) s_base = atomicAdd(&g_candCount[b], cnt);
    __syncthreads();
    unsigned base = s_base;
    for (unsigned i = threadIdx.x; i < cnt; i += blockDim.x) {
        unsigned pos = base + i;
        if (pos < CAND_CAP) g_cand[b][pos] = s_buf[i];
    }
}

// -------- K4: histogram candidates' next 12 bits + select sub-bin b2 (fused) --------
__global__ void k_scan2() {
    __shared__ unsigned a[H_SIZE];
    __shared__ unsigned t[H_SIZE];
    __shared__ int s_bin; __shared__ unsigned s_above;
    int b = blockIdx.x;
    for (int i = threadIdx.x; i < H_SIZE; i += blockDim.x) a[i] = 0u;
    __syncthreads();
    unsigned cnt = g_candCount[b];
    if (cnt > CAND_CAP) cnt = CAND_CAP;
    for (unsigned i = threadIdx.x; i < cnt; i += blockDim.x)
        atomicAdd(&a[(g_cand[b][i].x >> 8) & 0xFFFu], 1u);
    __syncthreads();
    unsigned target = KSEL - g_g1[b];   // >= 1 by construction
    scan_find2(a, t, target, &s_bin, &s_above);
    if (threadIdx.x == 0) { g_b2[b] = s_bin; g_rem[b] = target - s_above; }
}

// -------- K5: resolve candidates vs 24-bit prefix --------
__global__ void k_cands(float* __restrict__ out) {
    int b = blockIdx.y;
    unsigned count = g_candCount[b];
    if (count > CAND_CAP) count = CAND_CAP;
    unsigned prefix24 = (((unsigned)g_b1[b]) << 12) | (unsigned)g_b2[b];
    float* ob = out + (size_t)b * NPB;
    unsigned stride = gridDim.x * blockDim.x;
    for (unsigned i = blockIdx.x * blockDim.x + threadIdx.x; i < count; i += stride) {
        uint2 e = g_cand[b][i];
        unsigned p24 = e.x >> 8;
        if (p24 > prefix24) {
            ob[e.y] = val_of(e.x);
        } else if (p24 == prefix24) {
            unsigned pos = atomicAdd(&g_cand2Count[b], 1u);
            if (pos < CAND2_CAP) g_cand2[b][pos] = e;
        }
    }
}

// -------- K6: exact k-th key via byte histogram; index-stable ties --------
__global__ void k_final(float* __restrict__ out) {
    int b = blockIdx.x;
    unsigned c = g_cand2Count[b];
    if (c > CAND2_CAP) c = CAND2_CAP;
    unsigned r = g_rem[b];
    __shared__ unsigned hist[256];
    __shared__ int s_byte; __shared__ unsigned s_t;
    for (int i = threadIdx.x; i < 256; i += blockDim.x) hist[i] = 0u;
    __syncthreads();
    for (unsigned i = threadIdx.x; i < c; i += blockDim.x)
        atomicAdd(&hist[g_cand2[b][i].x & 0xFFu], 1u);
    __syncthreads();
    if (threadIdx.x == 0) {
        unsigned acc = 0; int byte = 0; unsigned t = 0;
        for (int bb = 255; bb >= 0; bb--) {
            unsigned cnt = hist[bb];
            if (acc < r && r <= acc + cnt) { byte = bb; t = r - acc; break; }
            acc += cnt;
        }
        s_byte = byte; s_t = t;
    }
    __syncthreads();
    int byte = s_byte; unsigned t = s_t;
    float* ob = out + (size_t)b * NPB;
    for (unsigned i = threadIdx.x; i < c; i += blockDim.x) {
        uint2 e = g_cand2[b][i];
        if ((int)(e.x & 0xFFu) > byte) ob[e.y] = val_of(e.x);
    }
    for (unsigned i = threadIdx.x; i < c; i += blockDim.x) {
        uint2 e = g_cand2[b][i];
        if ((int)(e.x & 0xFFu) == byte) {
            unsigned rank = 0;
            for (unsigned j = 0; j < c; j++) {
                uint2 f = g_cand2[b][j];
                if ((int)(f.x & 0xFFu) == byte && f.y < e.y) rank++;
            }
            if (rank < t) ob[e.y] = val_of(e.x);
        }
    }
}

extern "C" void kernel_launch(void* const* d_in, const int* in_sizes, int n_in,
                              void* d_out, int out_size) {
    const float* in = (const float*)d_in[0];
    float* out = (float*)d_out;
    (void)in_sizes; (void)n_in; (void)out_size;

    dim3 big(GRIDX, BATCH, 1);

    k_zero<<<64, 256>>>();
    k_hist1<<<big, TPB>>>(in);
    k_scan1<<<BATCH, 256>>>();
    k_partition<<<big, TPB>>>(in, out);
    k_scan2<<<BATCH, 256>>>();
    k_cands<<<dim3(32, BATCH, 1), 256>>>(out);
    k_final<<<BATCH, 256>>>(out);
}